// round 17
// baseline (speedup 1.0000x reference)
#include <cuda_runtime.h>
#include <cuda_fp16.h>
#include <cstdint>

// out[b,s,f] = scale * x[b,s,:] @ W, W = kernel ? +1 : -1
// GEMM: M=16384, K=1024, N=1024. mma.sync m16n8k16, fp32 accum.
// R17: prep distributed across ALL GEMM CTAs (no dedicated prep CTAs, no
// wave-1 dilution). m-tile t's fp32->fp16 convert is split 8 ways across its
// own consumer group (bids 8t..8t+7); groups 0..15 also pack their nb-slice
// of B. Arrival = idempotent atomicOr bitmask (replay-safe) + ld.acquire
// spin. Deadlock-free: bid-ordered dispatch => lowest unfinished group is
// fully launched; members convert BEFORE spinning. GEMM body = R13 verbatim.

#define M_TOTAL 16384
#define N_TOTAL 1024
#define K_TOTAL 1024

#define BM 128
#define BN 128
#define BK 64
#define STAGES 4
#define NCHUNK (K_TOTAL / BK)      // 16
#define ASTRIDE 144                // A smem row: 128B data + 16B pad (conflict-free ldsm)
#define A_SM_BYTES (BM * ASTRIDE)  // 18432
#define B_SM_BYTES 8192            // 2 k-subs x 2 nb-blocks x 2048B fragment bytes
#define STAGE_BYTES (A_SM_BYTES + B_SM_BYTES)   // 26624
#define SM_TILES 1024
#define SMEM_TOTAL (SM_TILES + STAGES * STAGE_BYTES)   // 107520 (2 CTAs/SM = 215KB)

__device__ __half g_xh[(size_t)M_TOTAL * K_TOTAL];        // 32 MB fp16 activations
__device__ unsigned char g_b8[(size_t)N_TOTAL * K_TOTAL]; // 1 MB fragment-ordered B bytes
__device__ unsigned g_conv_mask[128];  // per m-tile: 8 slice bits (BSS zero; idempotent)
__device__ unsigned g_pack_mask[16];   // per nb-slice: 8 portion bits

// ---------------- helpers ----------------
__device__ __forceinline__ uint32_t smem_u32(const void* p) {
    uint32_t a;
    asm("{ .reg .u64 t; cvta.to.shared.u64 t, %1; cvt.u32.u64 %0, t; }" : "=r"(a) : "l"(p));
    return a;
}
__device__ __forceinline__ void cp_async16(uint32_t dst, const void* src) {
    asm volatile("cp.async.cg.shared.global [%0], [%1], 16;" :: "r"(dst), "l"(src) : "memory");
}
__device__ __forceinline__ void ldsm_x4(uint32_t& r0, uint32_t& r1, uint32_t& r2, uint32_t& r3,
                                        uint32_t addr) {
    asm volatile("ldmatrix.sync.aligned.m8n8.x4.shared.b16 {%0,%1,%2,%3}, [%4];"
                 : "=r"(r0), "=r"(r1), "=r"(r2), "=r"(r3) : "r"(addr));
}
__device__ __forceinline__ void lds128(uint32_t& r0, uint32_t& r1, uint32_t& r2, uint32_t& r3,
                                       uint32_t addr) {
    asm volatile("ld.shared.v4.u32 {%0,%1,%2,%3}, [%4];"
                 : "=r"(r0), "=r"(r1), "=r"(r2), "=r"(r3) : "r"(addr));
}
__device__ __forceinline__ uint32_t prmt(uint32_t a, uint32_t sel) {
    uint32_t d;
    asm("prmt.b32 %0, %1, %2, %3;" : "=r"(d) : "r"(a), "r"(0u), "r"(sel));
    return d;
}
__device__ __forceinline__ uint4 cvt8(float4 f0, float4 f1) {
    __half2 h[4];
    h[0] = __floats2half2_rn(f0.x, f0.y);
    h[1] = __floats2half2_rn(f0.z, f0.w);
    h[2] = __floats2half2_rn(f1.x, f1.y);
    h[3] = __floats2half2_rn(f1.z, f1.w);
    return *(uint4*)h;
}
__device__ __forceinline__ void mma16816(float* d, const uint32_t* a, const uint32_t* b) {
    asm volatile(
        "mma.sync.aligned.m16n8k16.row.col.f32.f16.f16.f32 "
        "{%0,%1,%2,%3}, {%4,%5,%6,%7}, {%8,%9}, {%0,%1,%2,%3};"
        : "+f"(d[0]), "+f"(d[1]), "+f"(d[2]), "+f"(d[3])
        : "r"(a[0]), "r"(a[1]), "r"(a[2]), "r"(a[3]), "r"(b[0]), "r"(b[1]));
}
__device__ __forceinline__ void mbar_wait_parity(uint32_t mbar, uint32_t parity) {
    uint32_t done;
    asm volatile(
        "{ .reg .pred p; mbarrier.try_wait.parity.acquire.cta.shared::cta.b64 p, [%1], %2; selp.b32 %0, 1, 0, p; }"
        : "=r"(done) : "r"(mbar), "r"(parity) : "memory");
    if (!done) {
        asm volatile(
            "{ .reg .pred P1;\n"
            "WL_%=: mbarrier.try_wait.parity.acquire.cta.shared::cta.b64 P1, [%0], %1, 0x989680;\n"
            "@P1 bra.uni WD_%=;\n"
            "bra.uni WL_%=;\n"
            "WD_%=: }"
            :: "r"(mbar), "r"(parity) : "memory");
    }
}
__device__ __forceinline__ void spin_mask_full(unsigned* p) {
    unsigned v;
    for (;;) {
        asm volatile("ld.acquire.gpu.global.u32 %0, [%1];" : "=r"(v) : "l"(p) : "memory");
        if (v == 0xFFu) break;
        asm volatile("nanosleep.u32 64;");
    }
}

// ---------------- fused kernel ----------------
__global__ __launch_bounds__(256, 2)
void gemm_kernel(const float* __restrict__ x, const void* __restrict__ kern,
                 const float* __restrict__ scale_ptr, float* __restrict__ out) {
    extern __shared__ __align__(16) char smem[];
    uint32_t sbase = smem_u32(smem);
    int bid = blockIdx.x;
    int tid = threadIdx.x;
    int lane = tid & 31;
    int wid = tid >> 5;

    int nIdx = bid & 7;                    // n-fastest: siblings of an m-tile are adjacent bids
    int mIdx = bid >> 3;                   // = group/tile id t
    int slice = nIdx;                      // this CTA's prep slice j within the group
    int n0 = nIdx * BN;
    int m0 = mIdx * BM;
    int nb0 = n0 >> 6;

    // ---------------- distributed prep ----------------
    // (a) groups 0..15: pack portion `slice` of B nb-slice `mIdx`
    if (mIdx < 16) {
        __shared__ int notw, noth;
        if (tid == 0) { notw = 0; noth = 0; }
        __syncthreads();
        const uint32_t* kw = (const uint32_t*)kern;
        for (int i = tid; i < 1024; i += 256) {
            uint32_t w = kw[i];
            if (!(w == 0u || w == 1u || w == 0x3F800000u)) notw = 1;
            uint32_t h0 = w & 0xFFFFu, h1 = w >> 16;
            if (!((h0 == 0u || h0 == 1u || h0 == 0x3F80u || h0 == 0x3C00u) &&
                  (h1 == 0u || h1 == 1u || h1 == 0x3F80u || h1 == 0x3C00u))) noth = 1;
        }
        __syncthreads();
        int width = (!notw) ? 4 : ((!noth) ? 2 : 1);

        int nb = mIdx;
        #pragma unroll
        for (int i = 0; i < 2; i++) {      // 512 16B-groups / 256 threads
            int f = slice * 512 + i * 256 + tid;   // f in [0,4096) for this nb
            int k32 = f >> 7;
            int rem = f & 127;             // ks*64 + q*32 + lane'
            int ks = rem >> 6;
            int q = (rem >> 5) & 1;
            int ln = rem & 31;
            int gid = (k32 * 16 + nb) * 128 + rem;
            unsigned char bytes[16];
            #pragma unroll
            for (int jj = 0; jj < 16; jj++) {
                int nt = q * 4 + (jj >> 2);
                int reg = (jj >> 1) & 1;
                int e = jj & 1;
                int n = nb * 64 + nt * 8 + (ln >> 2);
                int k = k32 * 32 + ks * 16 + reg * 8 + 2 * (ln & 3) + e;
                size_t idx = (size_t)k * N_TOTAL + n;
                bool v = (width == 4) ? (((const uint32_t*)kern)[idx] != 0u)
                       : (width == 2) ? (((const uint16_t*)kern)[idx] != 0u)
                                      : (((const uint8_t*)kern)[idx] != 0u);
                bytes[jj] = v ? 0x3C : 0xBC;    // fp16 high byte of +1 / -1
            }
            *(uint4*)&g_b8[(size_t)gid * 16] = *(uint4*)bytes;
        }
    }

    // (b) all CTAs: convert 16 rows of their own m-tile (rows mIdx*128 + slice*16 ..)
    {
        size_t base = ((size_t)mIdx * BM + slice * 16) * K_TOTAL;  // halfs
        #pragma unroll
        for (int i = 0; i < 8; i++) {      // 2048 uint4 / 256 threads
            size_t off = base + (size_t)(i * 256 + tid) * 8;
            float4 f0 = *(const float4*)(x + off);
            float4 f1 = *(const float4*)(x + off + 4);
            *(uint4*)&g_xh[off] = cvt8(f0, f1);
        }
    }

    // publish + wait dependencies (tid 0), init mbarriers, then one barrier
    __threadfence();
    __syncthreads();
    if (tid == 0) {
        atomicOr(&g_conv_mask[mIdx], 1u << slice);
        if (mIdx < 16) atomicOr(&g_pack_mask[mIdx], 1u << slice);
        #pragma unroll
        for (int s = 0; s < STAGES; s++) {
            asm volatile("mbarrier.init.shared.b64 [%0], %1;" :: "r"(sbase + s * 8), "r"(256) : "memory");
            asm volatile("mbarrier.init.shared.b64 [%0], %1;" :: "r"(sbase + 32 + s * 8), "r"(256) : "memory");
        }
        spin_mask_full(&g_conv_mask[mIdx]);
        spin_mask_full(&g_pack_mask[nb0]);
        spin_mask_full(&g_pack_mask[nb0 + 1]);
    }
    __syncthreads();

    // ---------------- GEMM (R13 body) ----------------
    // warp tile: 32(M) x 64(N); warps laid out 4(M) x 2(N)
    int wm = (wid & 3) * 32;
    int wn = (wid >> 2) * 64;
    int nbl = wn >> 6;

    auto load_stage = [&](int kc, int s) {   // kc in units of BK=64
        uint32_t sA = sbase + SM_TILES + s * STAGE_BYTES;
        uint32_t sB = sA + A_SM_BYTES;
        #pragma unroll
        for (int i = 0; i < 4; i++) {           // A: 1024 x 16B chunks / 256 threads
            int c = tid + i * 256;
            int row = c >> 3, seg = c & 7;
            cp_async16(sA + row * ASTRIDE + seg * 16,
                       &g_xh[(size_t)(m0 + row) * K_TOTAL + kc * BK + seg * 8]);
        }
        #pragma unroll
        for (int i = 0; i < 2; i++) {           // B: 512 x 16B fragment-byte chunks
            int c = tid + i * 256;
            int sub = c >> 8;
            int rem = c & 255;
            int nbl_t = rem >> 7;
            int off = (rem & 127) * 16;
            cp_async16(sB + sub * 4096 + nbl_t * 2048 + off,
                       &g_b8[((size_t)((kc * 2 + sub) * 16 + nb0 + nbl_t)) * 2048 + off]);
        }
        asm volatile("cp.async.mbarrier.arrive.noinc.shared::cta.b64 [%0];"
                     :: "r"(sbase + s * 8) : "memory");
    };

    // prologue: fill stages 0..2 with chunks 0..2
    #pragma unroll
    for (int s = 0; s < STAGES - 1; s++)
        load_stage(s, s);

    float acc[2][8][4];
    #pragma unroll
    for (int mt = 0; mt < 2; mt++)
        #pragma unroll
        for (int nt = 0; nt < 8; nt++)
            #pragma unroll
            for (int j = 0; j < 4; j++) acc[mt][nt][j] = 0.0f;

    // A ldmatrix lane-address components (validated mapping)
    int r8 = lane & 7;
    int agrp_row = ((lane >> 3) & 1) * 8;
    int agrp_col = (lane >> 4) * 16;

    for (int kc = 0; kc < NCHUNK; kc++) {
        // -------- producer: fill stage for chunk kc+3 --------
        int pf = kc + STAGES - 1;
        if (pf < NCHUNK) {
            int ps = pf & (STAGES - 1);
            int rp = pf >> 2;
            if (rp >= 1)
                mbar_wait_parity(sbase + 32 + ps * 8, (rp - 1) & 1);
            load_stage(pf, ps);
        }

        // -------- consumer: chunk kc (4 k16 steps) --------
        int s = kc & (STAGES - 1);
        int r = kc >> 2;
        mbar_wait_parity(sbase + s * 8, r & 1);

        uint32_t sA = sbase + SM_TILES + s * STAGE_BYTES;
        uint32_t sB = sA + A_SM_BYTES;

        #pragma unroll
        for (int ks = 0; ks < 4; ks++) {
            int sub = ks >> 1, ksl = ks & 1;
            uint32_t bw[8];
            uint32_t baddr = sB + sub * 4096 + nbl * 2048 + ksl * 1024 + lane * 16;
            lds128(bw[0], bw[1], bw[2], bw[3], baddr);
            lds128(bw[4], bw[5], bw[6], bw[7], baddr + 512);
            uint32_t b[8][2];
            #pragma unroll
            for (int nt = 0; nt < 8; nt++) {
                b[nt][0] = prmt(bw[nt], 0x1404u);   // [00,H(e0),00,H(e1)]
                b[nt][1] = prmt(bw[nt], 0x3424u);
            }
            #pragma unroll
            for (int mt = 0; mt < 2; mt++) {
                int row = wm + mt * 16 + agrp_row + r8;
                uint32_t a[4];
                ldsm_x4(a[0], a[1], a[2], a[3], sA + row * ASTRIDE + ks * 32 + agrp_col);
                #pragma unroll
                for (int nt = 0; nt < 8; nt++)
                    mma16816(acc[mt][nt], a, b[nt]);
            }
        }
        asm volatile("mbarrier.arrive.shared.b64 _, [%0];" :: "r"(sbase + 32 + s * 8) : "memory");
    }

    // ---- epilogue: scaled fp32 stores, one 32B sector per lane-quad ----
    float sc = *scale_ptr;
    int gq = lane >> 2, t = lane & 3;
    #pragma unroll
    for (int mt = 0; mt < 2; mt++) {
        #pragma unroll
        for (int nt = 0; nt < 8; nt++) {
            int row = m0 + wm + mt * 16 + gq;
            int col = n0 + wn + nt * 8 + 2 * t;
            float2 v0 = make_float2(acc[mt][nt][0] * sc, acc[mt][nt][1] * sc);
            float2 v1 = make_float2(acc[mt][nt][2] * sc, acc[mt][nt][3] * sc);
            *(float2*)(out + (size_t)row * N_TOTAL + col) = v0;
            *(float2*)(out + (size_t)(row + 8) * N_TOTAL + col) = v1;
        }
    }
}

// ---------------- launch ----------------
extern "C" void kernel_launch(void* const* d_in, const int* in_sizes, int n_in,
                              void* d_out, int out_size) {
    // identify inputs by element count (robust to ordering)
    const float* x = nullptr;
    const void* kern = nullptr;
    const float* scale = nullptr;
    for (int i = 0; i < n_in; i++) {
        if (in_sizes[i] == M_TOTAL * K_TOTAL) x = (const float*)d_in[i];
        else if (in_sizes[i] == K_TOTAL * N_TOTAL) kern = (const void*)d_in[i];
        else if (in_sizes[i] == 1) scale = (const float*)d_in[i];
    }
    float* out = (float*)d_out;

    cudaFuncSetAttribute(gemm_kernel, cudaFuncAttributeMaxDynamicSharedMemorySize, SMEM_TOTAL);

    // single launch, grid = 1024 GEMM CTAs (n-fastest within each m-tile);
    // prep is distributed inside
    gemm_kernel<<<(N_TOTAL / BN) * (M_TOTAL / BM), 256, SMEM_TOTAL>>>(x, kern, scale, out);
}